// round 5
// baseline (speedup 1.0000x reference)
#include <cuda_runtime.h>
#include <cuda_bf16.h>
#include <math.h>
#include <stdint.h>

// Problem constants
#define T_DIM 128
#define B_DIM 64
#define H_DIM 512
#define E_DIM 256
#define V_DIM 32000
#define VT_DIM (V_DIM + T_DIM)   // 32128
#define EPSC 1e-10f

// ---------------- scratch ----------------
static constexpr size_t OFF_SPART  = 0;                                   // 4 x B*T score partials
static constexpr size_t OFF_RPART  = OFF_SPART + 4 * (size_t)B_DIM * T_DIM;
static constexpr size_t OFF_HW1    = OFF_RPART + 4 * (size_t)B_DIM * T_DIM;
static constexpr size_t OFF_CTX    = OFF_HW1   + (size_t)B_DIM * H_DIM;
static constexpr size_t OFF_X      = OFF_CTX   + (size_t)B_DIM * H_DIM;
static constexpr size_t OFF_GI     = OFF_X     + (size_t)B_DIM * (E_DIM + H_DIM);
static constexpr size_t OFF_GH     = OFF_GI    + (size_t)B_DIM * 3 * H_DIM;
static constexpr size_t OFF_HNEW   = OFF_GH    + (size_t)B_DIM * 3 * H_DIM;
static constexpr size_t OFF_XP     = OFF_HNEW  + (size_t)B_DIM * H_DIM;
static constexpr size_t OFF_GEN    = OFF_XP    + (size_t)B_DIM * 2 * H_DIM;
static constexpr size_t OFF_SCAT   = OFF_GEN   + (size_t)B_DIM * V_DIM;
static constexpr size_t OFF_STATS  = OFF_SCAT  + (size_t)B_DIM * VT_DIM;
static constexpr size_t SCRATCH_TOTAL = OFF_STATS + (size_t)B_DIM * 8;

__device__ __align__(16) float g_scratch[SCRATCH_TOTAL];

// ================= warp MMA helpers (baseline PTX, sm_80+) ====
__device__ __forceinline__ uint32_t smem_u32(const void* p) {
    uint32_t a;
    asm("{ .reg .u64 t; cvta.to.shared.u64 t, %1; cvt.u32.u64 %0, t; }" : "=r"(a) : "l"(p));
    return a;
}
__device__ __forceinline__ void ldsm4(uint32_t* r, uint32_t addr) {
    asm volatile("ldmatrix.sync.aligned.m8n8.x4.shared.b16 {%0,%1,%2,%3}, [%4];"
        : "=r"(r[0]), "=r"(r[1]), "=r"(r[2]), "=r"(r[3]) : "r"(addr));
}
__device__ __forceinline__ void mma_bf16(float* c, const uint32_t* a, const uint32_t* b) {
    asm volatile("mma.sync.aligned.m16n8k16.row.col.f32.bf16.bf16.f32 "
        "{%0,%1,%2,%3}, {%4,%5,%6,%7}, {%8,%9}, {%0,%1,%2,%3};"
        : "+f"(c[0]), "+f"(c[1]), "+f"(c[2]), "+f"(c[3])
        : "r"(a[0]), "r"(a[1]), "r"(a[2]), "r"(a[3]), "r"(b[0]), "r"(b[1]));
}
__device__ __forceinline__ void cvt_split(float4 v, uint2& hi, uint2& lo) {
    uint32_t h01, h23;
    asm("cvt.rn.bf16x2.f32 %0, %1, %2;" : "=r"(h01) : "f"(v.y), "f"(v.x));
    asm("cvt.rn.bf16x2.f32 %0, %1, %2;" : "=r"(h23) : "f"(v.w), "f"(v.z));
    float h0 = __uint_as_float(h01 << 16);
    float h1 = __uint_as_float(h01 & 0xffff0000u);
    float h2 = __uint_as_float(h23 << 16);
    float h3 = __uint_as_float(h23 & 0xffff0000u);
    uint32_t l01, l23;
    asm("cvt.rn.bf16x2.f32 %0, %1, %2;" : "=r"(l01) : "f"(v.y - h1), "f"(v.x - h0));
    asm("cvt.rn.bf16x2.f32 %0, %1, %2;" : "=r"(l23) : "f"(v.w - h3), "f"(v.z - h2));
    hi = make_uint2(h01, h23);
    lo = make_uint2(l01, l23);
}

// ================= tensor-core GEMM (HMMA, bf16x3 split) =================
// C[m,n] = sum_k A[m,k] * B[n,k]; fp32 in/out. CTA tile 64 x 128, BK=32, 256 thr, 2 CTA/SM.
// If red_out != null: fused epilogue
//   red[m] = sum_n wgt(n,b) * tanh(acc[m,n] + add_bh[b,n] + bias_n[n]), b = m & 63, t = m >> 6
static constexpr int ROWB   = 80;                // bytes per smem row (32 bf16 + pad)
static constexpr int TILEA  = 64 * ROWB;         // 5120
static constexpr int TILEB  = 128 * ROWB;        // 10240
static constexpr int STAGEB = 2 * TILEA + 2 * TILEB;  // 30720
static constexpr int TG_SMEM = 2 * STAGEB;            // 61440

__global__ void __launch_bounds__(256, 2) tgemm(
    const float* __restrict__ A, const float* __restrict__ B, float* __restrict__ C,
    int M_A, int M_C, int K, int lda, int ldb, int ldc,
    const float* __restrict__ add_bh, const float* __restrict__ bias_n,
    const float* __restrict__ wgt_n,  const float* __restrict__ wgt_bh,
    float* __restrict__ red_out)
{
    extern __shared__ char smem[];
    const uint32_t sb = smem_u32(smem);
    const int tid  = threadIdx.x;
    const int lane = tid & 31;
    const int warp = tid >> 5;
    const int wy   = warp >> 2;      // 0..1  (32-row half)
    const int wx   = warp & 3;       // 0..3  (32-col quarter)
    const int m0   = blockIdx.y * 64;
    const int n0   = blockIdx.x * 128;

    float acc[2][4][4];
#pragma unroll
    for (int i = 0; i < 2; i++)
#pragma unroll
        for (int j = 0; j < 4; j++)
#pragma unroll
            for (int q = 0; q < 4; q++) acc[i][j][q] = 0.0f;

    const int nchunk = K >> 5;
    float4 ra[2], rb[4];

    auto load_regs = [&](int c) {
        const int k0 = c << 5;
#pragma unroll
        for (int i = 0; i < 2; i++) {
            int id  = tid + (i << 8);
            int row = id >> 3;
            int kq  = id & 7;
            ra[i] = (m0 + row < M_A)
                  ? *(const float4*)&A[(size_t)(m0 + row) * lda + k0 + (kq << 2)]
                  : make_float4(0.f, 0.f, 0.f, 0.f);
        }
#pragma unroll
        for (int i = 0; i < 4; i++) {
            int id  = tid + (i << 8);
            int row = id >> 3;
            int kq  = id & 7;
            rb[i] = *(const float4*)&B[(size_t)(n0 + row) * ldb + k0 + (kq << 2)];
        }
    };
    auto store_smem = [&](int stage) {
        char* base = smem + stage * STAGEB;
        uint2 hi, lo;
#pragma unroll
        for (int i = 0; i < 2; i++) {
            int id  = tid + (i << 8);
            int row = id >> 3;
            int kq  = id & 7;
            int off = row * ROWB + (kq << 3);
            cvt_split(ra[i], hi, lo);
            *(uint2*)(base + off)         = hi;           // A_hi
            *(uint2*)(base + TILEA + off) = lo;           // A_lo
        }
#pragma unroll
        for (int i = 0; i < 4; i++) {
            int id  = tid + (i << 8);
            int row = id >> 3;
            int kq  = id & 7;
            int off = row * ROWB + (kq << 3);
            cvt_split(rb[i], hi, lo);
            *(uint2*)(base + 2 * TILEA + off)         = hi; // B_hi
            *(uint2*)(base + 2 * TILEA + TILEB + off) = lo; // B_lo
        }
    };
    auto compute = [&](int stage) {
        const uint32_t s0 = sb + stage * STAGEB;
        const int q = lane >> 3, r = lane & 7;
#pragma unroll
        for (int ks = 0; ks < 32; ks += 16) {
            uint32_t a_hi[2][4], a_lo[2][4], b_hi[4][2], b_lo[4][2];
            {
                int arow = wy * 32 + ((q & 1) ? 8 : 0) + r;
                int acol = ks + ((q & 2) ? 8 : 0);
                uint32_t addr = s0 + arow * ROWB + acol * 2;
#pragma unroll
                for (int mt = 0; mt < 2; mt++) {
                    ldsm4(a_hi[mt], addr + mt * (16 * ROWB));
                    ldsm4(a_lo[mt], addr + TILEA + mt * (16 * ROWB));
                }
            }
            {
                int brow = wx * 32 + ((q & 2) ? 8 : 0) + r;
                int bcol = ks + ((q & 1) ? 8 : 0);
                uint32_t addr = s0 + 2 * TILEA + brow * ROWB + bcol * 2;
#pragma unroll
                for (int np = 0; np < 2; np++) {
                    ldsm4(&b_hi[np * 2][0], addr + np * (16 * ROWB));
                    ldsm4(&b_lo[np * 2][0], addr + TILEB + np * (16 * ROWB));
                }
            }
            // pass-separated MMAs: 8 independent accumulators between same-acc reuse
#pragma unroll
            for (int mt = 0; mt < 2; mt++)
#pragma unroll
                for (int nt = 0; nt < 4; nt++)
                    mma_bf16(acc[mt][nt], a_hi[mt], b_hi[nt]);
#pragma unroll
            for (int mt = 0; mt < 2; mt++)
#pragma unroll
                for (int nt = 0; nt < 4; nt++)
                    mma_bf16(acc[mt][nt], a_hi[mt], b_lo[nt]);
#pragma unroll
            for (int mt = 0; mt < 2; mt++)
#pragma unroll
                for (int nt = 0; nt < 4; nt++)
                    mma_bf16(acc[mt][nt], a_lo[mt], b_hi[nt]);
        }
    };

    // pipelined main loop
    load_regs(0);
    store_smem(0);
    if (nchunk > 1) load_regs(1);
    __syncthreads();
    for (int c = 0; c < nchunk; c++) {
        if (c + 1 < nchunk) store_smem((c + 1) & 1);
        if (c + 2 < nchunk) load_regs(c + 2);
        compute(c & 1);
        __syncthreads();
    }

    const int g = lane >> 2, tig = lane & 3;

    if (red_out) {
        float* red = (float*)smem;   // [4][64], safe after final sync
#pragma unroll
        for (int mt = 0; mt < 2; mt++) {
            int rl0 = wy * 32 + mt * 16 + g;
            int rl1 = rl0 + 8;
            int b0 = (m0 + rl0) & 63, b1 = (m0 + rl1) & 63;
            float p0 = 0.f, p1 = 0.f;
#pragma unroll
            for (int nt = 0; nt < 4; nt++) {
                int col = n0 + wx * 32 + nt * 8 + tig * 2;
#pragma unroll
                for (int cc = 0; cc < 2; cc++) {
                    int cg = col + cc;
                    float bias = bias_n[cg];
                    float a0 = add_bh ? add_bh[(size_t)b0 * H_DIM + cg] : 0.f;
                    float a1 = add_bh ? add_bh[(size_t)b1 * H_DIM + cg] : 0.f;
                    float w0 = wgt_n ? wgt_n[cg] : wgt_bh[(size_t)b0 * H_DIM + cg];
                    float w1 = wgt_n ? wgt_n[cg] : wgt_bh[(size_t)b1 * H_DIM + cg];
                    p0 += w0 * tanhf(acc[mt][nt][cc]     + a0 + bias);
                    p1 += w1 * tanhf(acc[mt][nt][2 + cc] + a1 + bias);
                }
            }
            p0 += __shfl_xor_sync(0xffffffffu, p0, 1);
            p0 += __shfl_xor_sync(0xffffffffu, p0, 2);
            p1 += __shfl_xor_sync(0xffffffffu, p1, 1);
            p1 += __shfl_xor_sync(0xffffffffu, p1, 2);
            if (tig == 0) { red[wx * 64 + rl0] = p0; red[wx * 64 + rl1] = p1; }
        }
        __syncthreads();
        if (tid < 64) {
            float s = red[tid] + red[64 + tid] + red[128 + tid] + red[192 + tid];
            int m = m0 + tid;
            red_out[(size_t)blockIdx.x * (B_DIM * T_DIM) + (m & 63) * T_DIM + (m >> 6)] = s;
        }
        return;
    }

    // plain store epilogue
#pragma unroll
    for (int mt = 0; mt < 2; mt++) {
        int row0 = m0 + wy * 32 + mt * 16 + g;
#pragma unroll
        for (int nt = 0; nt < 4; nt++) {
            int col = n0 + wx * 32 + nt * 8 + tig * 2;
            if (row0 < M_C) {
                *(float2*)&C[(size_t)row0 * ldc + col] = make_float2(acc[mt][nt][0], acc[mt][nt][1]);
                *(float2*)&C[(size_t)(row0 + 8) * ldc + col] = make_float2(acc[mt][nt][2], acc[mt][nt][3]);
            }
        }
    }
}

// ================= elementwise / reduction kernels =================

__global__ void k_zero(float* p, int n)
{
    for (int i = blockIdx.x * blockDim.x + threadIdx.x; i < n; i += gridDim.x * blockDim.x)
        p[i] = 0.0f;
}

// fused: alpha softmax (from partials) + ctx + build x = [emb[z], ctx]
__global__ void __launch_bounds__(256) k_attn(
    const float* __restrict__ part, const int* __restrict__ z,
    const float* __restrict__ emb,  const float* __restrict__ enc,
    float* __restrict__ ctx, float* __restrict__ x)
{
    int b = blockIdx.x, tid = threadIdx.x;
    __shared__ float al[T_DIM];
    __shared__ float sm[T_DIM];
    if (tid < T_DIM) {
        int idx = b * T_DIM + tid;
        float v = part[idx] + part[B_DIM * T_DIM + idx]
                + part[2 * B_DIM * T_DIM + idx] + part[3 * B_DIM * T_DIM + idx];
        al[tid] = v; sm[tid] = v;
    }
    __syncthreads();
    for (int o = 64; o > 0; o >>= 1) { if (tid < o) sm[tid] = fmaxf(sm[tid], sm[tid + o]); __syncthreads(); }
    float mx = sm[0]; __syncthreads();
    if (tid < T_DIM) { float e = expf(al[tid] - mx); al[tid] = e; sm[tid] = e; }
    __syncthreads();
    for (int o = 64; o > 0; o >>= 1) { if (tid < o) sm[tid] += sm[tid + o]; __syncthreads(); }
    float inv = 1.0f / sm[0];

    // ctx: 512 h, 256 threads -> 2 consecutive h per thread
    int h = tid * 2;
    float2 acc = make_float2(0.f, 0.f);
    for (int t = 0; t < T_DIM; t++) {
        float a = al[t] * inv;
        float2 e = *(const float2*)&enc[((size_t)t * B_DIM + b) * H_DIM + h];
        acc.x += a * e.x; acc.y += a * e.y;
    }
    *(float2*)&ctx[b * H_DIM + h] = acc;
    *(float2*)&x[(size_t)b * (E_DIM + H_DIM) + E_DIM + h] = acc;
    // emb part: 256 threads x 1 elem (E=256)
    x[(size_t)b * (E_DIM + H_DIM) + tid] = emb[(size_t)z[b] * E_DIM + tid];
}

__global__ void k_gru(const float* __restrict__ gi, const float* __restrict__ gh,
                      const float* __restrict__ bih, const float* __restrict__ bhh,
                      const float* __restrict__ h_prev, const float* __restrict__ ctx,
                      float* __restrict__ hnew, float* __restrict__ xp,
                      float* __restrict__ out)
{
    int b = blockIdx.x, h = threadIdx.x;
    const float* gib = gi + (size_t)b * 3 * H_DIM;
    const float* ghb = gh + (size_t)b * 3 * H_DIM;
    float ir  = gib[h]              + bih[h];
    float iz  = gib[H_DIM + h]      + bih[H_DIM + h];
    float in_ = gib[2 * H_DIM + h]  + bih[2 * H_DIM + h];
    float hr  = ghb[h]              + bhh[h];
    float hz  = ghb[H_DIM + h]      + bhh[H_DIM + h];
    float hn  = ghb[2 * H_DIM + h]  + bhh[2 * H_DIM + h];
    float r  = 1.0f / (1.0f + expf(-(ir + hr)));
    float zz = 1.0f / (1.0f + expf(-(iz + hz)));
    float n  = tanhf(in_ + r * hn);
    float hp = h_prev[b * H_DIM + h];
    float v  = (1.0f - zz) * n + zz * hp;
    hnew[b * H_DIM + h] = v;
    out[b * H_DIM + h] = v;
    out[B_DIM * H_DIM + b * H_DIM + h] = v;
    xp[b * 2 * H_DIM + h] = v;
    xp[b * 2 * H_DIM + H_DIM + h] = ctx[b * H_DIM + h];
}

// stats + parallel deterministic scatter; raw = sum of 4 partials
__global__ void k_copystats(const float* __restrict__ rpart, const int* __restrict__ u_input,
                            float* __restrict__ scat, float* __restrict__ stats)
{
    int b = blockIdx.x, t = threadIdx.x;
    int idx0 = b * T_DIM + t;
    __shared__ float sm[T_DIM];
    __shared__ float exm[T_DIM];
    __shared__ int   sidx[T_DIM];
    float v = rpart[idx0] + rpart[B_DIM * T_DIM + idx0]
            + rpart[2 * B_DIM * T_DIM + idx0] + rpart[3 * B_DIM * T_DIM + idx0];
    sm[t] = v; __syncthreads();
    for (int o = 64; o > 0; o >>= 1) { if (t < o) sm[t] = fmaxf(sm[t], sm[t + o]); __syncthreads(); }
    float cmax = sm[0]; __syncthreads();

    float e = expf(v - cmax);
    int tok = u_input[t * B_DIM + b];
    sidx[t] = (tok == 2) ? (V_DIM + t) : tok;
    float em = (tok != 0) ? e : 0.0f;
    exm[t] = em;

    sm[t] = e; __syncthreads();
    for (int o = 64; o > 0; o >>= 1) { if (t < o) sm[t] += sm[t + o]; __syncthreads(); }
    float total = sm[0]; __syncthreads();

    sm[t] = em; __syncthreads();
    for (int o = 64; o > 0; o >>= 1) { if (t < o) sm[t] += sm[t + o]; __syncthreads(); }
    float sum_exm = sm[0]; __syncthreads();

    int idx = sidx[t];
    bool first = true;
    for (int i = 0; i < t; i++) if (sidx[i] == idx) { first = false; break; }
    float a = 0.0f;
    if (first) {
        for (int i = t; i < T_DIM; i++) if (sidx[i] == idx) a += exm[i];
        scat[(size_t)b * VT_DIM + idx] = a;
    }
    sm[t] = a; __syncthreads();
    for (int o = 64; o > 0; o >>= 1) { if (t < o) sm[t] = fmaxf(sm[t], sm[t + o]); __syncthreads(); }
    if (t == 0) {
        stats[b * 8 + 0] = cmax;
        stats[b * 8 + 1] = total;
        stats[b * 8 + 2] = sum_exm;
        stats[b * 8 + 3] = sm[0];
    }
}

__global__ void k_reduce(const float* __restrict__ gen, const float* __restrict__ projb,
                         float* __restrict__ stats)
{
    int b = blockIdx.x, tid = threadIdx.x;
    float m = -1e30f, s = 0.0f;
    for (int v = tid; v < V_DIM; v += 512) {
        float l = gen[(size_t)b * V_DIM + v] + projb[v];
        float mn = fmaxf(m, l);
        s = s * expf(m - mn) + expf(l - mn);
        m = mn;
    }
    __shared__ float ms[512], ss[512];
    ms[tid] = m; ss[tid] = s; __syncthreads();
    for (int o = 256; o > 0; o >>= 1) {
        if (tid < o) {
            float m2 = ms[tid + o], s2 = ss[tid + o];
            float mn = fmaxf(ms[tid], m2);
            ss[tid] = ss[tid] * expf(ms[tid] - mn) + s2 * expf(m2 - mn);
            ms[tid] = mn;
        }
        __syncthreads();
    }
    if (tid == 0) {
        float cmax = stats[b * 8 + 0];
        float total = stats[b * 8 + 1];
        float sum_exm = stats[b * 8 + 2];
        float smax = stats[b * 8 + 3];
        float mg = ms[0], sg = ss[0];
        float mc = logf(EPSC * total + (1.0f - EPSC) * smax) + cmax;
        float M = fmaxf(mg, mc);
        float A = expf(cmax - M);
        float S = sg * expf(mg - M)
                + A * (EPSC * total * (float)VT_DIM + (1.0f - EPSC) * sum_exm);
        stats[b * 8 + 4] = M;
        stats[b * 8 + 5] = S;
        stats[b * 8 + 6] = A;
    }
}

__global__ void k_final(const float* __restrict__ gen, const float* __restrict__ projb,
                        const float* __restrict__ scat, const float* __restrict__ stats,
                        float* __restrict__ out)
{
    int i = blockIdx.x * blockDim.x + threadIdx.x;
    if (i >= B_DIM * VT_DIM) return;
    int b = i / VT_DIM;
    int j = i % VT_DIM;
    float M = stats[b * 8 + 4];
    float S = stats[b * 8 + 5];
    float A = stats[b * 8 + 6];
    float total = stats[b * 8 + 1];
    float val = A * (EPSC * total + (1.0f - EPSC) * scat[i]) / S;
    if (j < V_DIM)
        val += expf(gen[(size_t)b * V_DIM + j] + projb[j] - M) / S;
    out[2 * B_DIM * H_DIM + i] = val;
}

// ================= host launcher =================
extern "C" void kernel_launch(void* const* d_in, const int* in_sizes, int n_in,
                              void* d_out, int out_size)
{
    const float* u_enc  = (const float*)d_in[0];
    const int*   z_tm1  = (const int*)  d_in[1];
    const float* h0     = (const float*)d_in[2];
    const int*   u_inp  = (const int*)  d_in[3];
    const float* emb    = (const float*)d_in[4];
    const float* attn_W = (const float*)d_in[5];
    const float* attn_b = (const float*)d_in[6];
    const float* attn_v = (const float*)d_in[7];
    const float* gWih   = (const float*)d_in[8];
    const float* gWhh   = (const float*)d_in[9];
    const float* gbih   = (const float*)d_in[10];
    const float* gbhh   = (const float*)d_in[11];
    const float* projW  = (const float*)d_in[12];
    const float* projb  = (const float*)d_in[13];
    const float* c1W    = (const float*)d_in[14];
    const float* c1b    = (const float*)d_in[15];
    float* out = (float*)d_out;

    float* base = nullptr;
    cudaGetSymbolAddress((void**)&base, g_scratch);
    float* spart  = base + OFF_SPART;
    float* rpart  = base + OFF_RPART;
    float* hW1    = base + OFF_HW1;
    float* ctx    = base + OFF_CTX;
    float* x      = base + OFF_X;
    float* gi     = base + OFF_GI;
    float* gh     = base + OFF_GH;
    float* hnew   = base + OFF_HNEW;
    float* xp     = base + OFF_XP;
    float* gen    = base + OFF_GEN;
    float* scat   = base + OFF_SCAT;
    float* stats  = base + OFF_STATS;

    cudaFuncSetAttribute(tgemm, cudaFuncAttributeMaxDynamicSharedMemorySize, TG_SMEM);

    const int MROWS = T_DIM * B_DIM;  // 8192

    // 0) zero the dense scatter buffer
    k_zero<<<512, 256>>>(scat, B_DIM * VT_DIM);

    // 1) hW1 = h0 @ W1^T
    tgemm<<<dim3(H_DIM / 128, 1), 256, TG_SMEM>>>(
        h0, attn_W, hW1, B_DIM, B_DIM, H_DIM, H_DIM, 2 * H_DIM, H_DIM,
        nullptr, nullptr, nullptr, nullptr, nullptr);

    // 2) energy GEMM with fused score reduction -> spart[4][B*T]
    tgemm<<<dim3(H_DIM / 128, MROWS / 64), 256, TG_SMEM>>>(
        u_enc, attn_W + H_DIM, nullptr, MROWS, 0, H_DIM, H_DIM, 2 * H_DIM, 0,
        hW1, attn_b, attn_v, nullptr, spart);

    // 3) fused alpha softmax + ctx + x
    k_attn<<<B_DIM, 256>>>(spart, z_tm1, emb, u_enc, ctx, x);

    // 4) GRU
    tgemm<<<dim3(3 * H_DIM / 128, 1), 256, TG_SMEM>>>(
        x, gWih, gi, B_DIM, B_DIM, E_DIM + H_DIM, E_DIM + H_DIM, E_DIM + H_DIM, 3 * H_DIM,
        nullptr, nullptr, nullptr, nullptr, nullptr);
    tgemm<<<dim3(3 * H_DIM / 128, 1), 256, TG_SMEM>>>(
        h0, gWhh, gh, B_DIM, B_DIM, H_DIM, H_DIM, H_DIM, 3 * H_DIM,
        nullptr, nullptr, nullptr, nullptr, nullptr);
    k_gru<<<B_DIM, H_DIM>>>(gi, gh, gbih, gbhh, h0, ctx, hnew, xp, out);

    // 5) copy GEMM with fused raw reduction -> rpart[4][B*T]
    tgemm<<<dim3(H_DIM / 128, MROWS / 64), 256, TG_SMEM>>>(
        u_enc, c1W, nullptr, MROWS, 0, H_DIM, H_DIM, H_DIM, 0,
        nullptr, c1b, nullptr, hnew, rpart);
    k_copystats<<<B_DIM, T_DIM>>>(rpart, u_inp, scat, stats);

    // 6) gen_score = [h_new, ctx] @ proj_W^T
    tgemm<<<dim3(V_DIM / 128, 1), 256, TG_SMEM>>>(
        xp, projW, gen, B_DIM, B_DIM, 2 * H_DIM, 2 * H_DIM, 2 * H_DIM, V_DIM,
        nullptr, nullptr, nullptr, nullptr, nullptr);

    // 7) global softmax reduction + final proba
    k_reduce<<<B_DIM, 512>>>(gen, projb, stats);
    k_final<<<(B_DIM * VT_DIM + 255) / 256, 256>>>(gen, projb, scat, stats, out);
}

// round 6
// speedup vs baseline: 1.4790x; 1.4790x over previous
#include <cuda_runtime.h>
#include <cuda_bf16.h>
#include <math.h>
#include <stdint.h>

// Problem constants
#define T_DIM 128
#define B_DIM 64
#define H_DIM 512
#define E_DIM 256
#define V_DIM 32000
#define VT_DIM (V_DIM + T_DIM)   // 32128
#define EPSC 1e-10f

// ---------------- scratch ----------------
static constexpr size_t OFF_SPART  = 0;
static constexpr size_t OFF_RPART  = OFF_SPART + 4 * (size_t)B_DIM * T_DIM;
static constexpr size_t OFF_HW1    = OFF_RPART + 4 * (size_t)B_DIM * T_DIM;
static constexpr size_t OFF_CTX    = OFF_HW1   + (size_t)B_DIM * H_DIM;
static constexpr size_t OFF_X      = OFF_CTX   + (size_t)B_DIM * H_DIM;
static constexpr size_t OFF_GI     = OFF_X     + (size_t)B_DIM * (E_DIM + H_DIM);
static constexpr size_t OFF_GH     = OFF_GI    + (size_t)B_DIM * 3 * H_DIM;
static constexpr size_t OFF_HNEW   = OFF_GH    + (size_t)B_DIM * 3 * H_DIM;
static constexpr size_t OFF_XP     = OFF_HNEW  + (size_t)B_DIM * H_DIM;
static constexpr size_t OFF_GEN    = OFF_XP    + (size_t)B_DIM * 2 * H_DIM;
static constexpr size_t OFF_SCAT   = OFF_GEN   + (size_t)B_DIM * V_DIM;
static constexpr size_t OFF_STATS  = OFF_SCAT  + (size_t)B_DIM * VT_DIM;
static constexpr size_t SCRATCH_TOTAL = OFF_STATS + (size_t)B_DIM * 8;

__device__ __align__(16) float g_scratch[SCRATCH_TOTAL];

// ================= tf32 MMA helpers (baseline PTX, sm_80+) ====
__device__ __forceinline__ uint32_t f2tf32(float x) {
    uint32_t r; asm("cvt.rna.tf32.f32 %0, %1;" : "=r"(r) : "f"(x)); return r;
}
__device__ __forceinline__ void mma_tf32(float* c, const uint32_t* a, const uint32_t* b) {
    asm volatile("mma.sync.aligned.m16n8k8.row.col.f32.tf32.tf32.f32 "
        "{%0,%1,%2,%3}, {%4,%5,%6,%7}, {%8,%9}, {%0,%1,%2,%3};"
        : "+f"(c[0]), "+f"(c[1]), "+f"(c[2]), "+f"(c[3])
        : "r"(a[0]), "r"(a[1]), "r"(a[2]), "r"(a[3]), "r"(b[0]), "r"(b[1]));
}

// ================= tensor-core GEMM (tf32 single pass) =================
// C[m,n] = sum_k A[m,k] * B[n,k]; fp32 in/out. CTA tile (32*MT) x 128, BK=32, 256 thr.
// Fused reduction epilogue when red_out != null (see R4).
static constexpr int SW = 36;   // words per smem row (32 tf32 + 4 pad) -> conflict-free

template<int MT>
__global__ void __launch_bounds__(256, MT == 2 ? 2 : 1) tgemm(
    const float* __restrict__ A, const float* __restrict__ B, float* __restrict__ C,
    int M_A, int M_C, int K, int lda, int ldb, int ldc,
    const float* __restrict__ add_bh, const float* __restrict__ bias_n,
    const float* __restrict__ wgt_n,  const float* __restrict__ wgt_bh,
    float* __restrict__ red_out)
{
    constexpr int ROWS = 32 * MT;          // CTA M rows
    constexpr int AW   = ROWS * SW;        // A tile words
    constexpr int BWW  = 128 * SW;         // B tile words
    constexpr int STW  = AW + BWW;         // stage words

    extern __shared__ uint32_t smw[];
    const int tid  = threadIdx.x;
    const int lane = tid & 31;
    const int warp = tid >> 5;
    const int wy   = warp >> 2;            // 0..1
    const int wx   = warp & 3;             // 0..3
    const int m0   = blockIdx.y * ROWS;
    const int n0   = blockIdx.x * 128;

    float acc[MT][4][4];
#pragma unroll
    for (int i = 0; i < MT; i++)
#pragma unroll
        for (int j = 0; j < 4; j++)
#pragma unroll
            for (int q = 0; q < 4; q++) acc[i][j][q] = 0.0f;

    const int nchunk = K >> 5;
    float4 ra[MT], rb[4];

    auto load_regs = [&](int c) {
        const int k0 = c << 5;
#pragma unroll
        for (int i = 0; i < MT; i++) {
            int id  = tid + (i << 8);
            int row = id >> 3;
            int kq  = id & 7;
            ra[i] = (m0 + row < M_A)
                  ? *(const float4*)&A[(size_t)(m0 + row) * lda + k0 + (kq << 2)]
                  : make_float4(0.f, 0.f, 0.f, 0.f);
        }
#pragma unroll
        for (int i = 0; i < 4; i++) {
            int id  = tid + (i << 8);
            int row = id >> 3;
            int kq  = id & 7;
            rb[i] = *(const float4*)&B[(size_t)(n0 + row) * ldb + k0 + (kq << 2)];
        }
    };
    auto store_smem = [&](int stage) {
        uint32_t* base = smw + stage * STW;
#pragma unroll
        for (int i = 0; i < MT; i++) {
            int id  = tid + (i << 8);
            int row = id >> 3;
            int kq  = id & 7;
            uint4 t = make_uint4(f2tf32(ra[i].x), f2tf32(ra[i].y), f2tf32(ra[i].z), f2tf32(ra[i].w));
            *(uint4*)&base[row * SW + (kq << 2)] = t;
        }
#pragma unroll
        for (int i = 0; i < 4; i++) {
            int id  = tid + (i << 8);
            int row = id >> 3;
            int kq  = id & 7;
            uint4 t = make_uint4(f2tf32(rb[i].x), f2tf32(rb[i].y), f2tf32(rb[i].z), f2tf32(rb[i].w));
            *(uint4*)&base[AW + row * SW + (kq << 2)] = t;
        }
    };
    auto compute = [&](int stage) {
        const uint32_t* As = smw + stage * STW;
        const uint32_t* Bs = As + AW;
        const int g = lane >> 2, c4 = lane & 3;
#pragma unroll
        for (int ks = 0; ks < 4; ks++) {
            const int kc = ks * 8 + c4;
            uint32_t af[MT][4], bf[4][2];
#pragma unroll
            for (int mt = 0; mt < MT; mt++) {
                const uint32_t* p = As + (wy * (MT * 16) + mt * 16 + g) * SW + kc;
                af[mt][0] = p[0];
                af[mt][1] = p[8 * SW];
                af[mt][2] = p[4];
                af[mt][3] = p[8 * SW + 4];
            }
#pragma unroll
            for (int nt = 0; nt < 4; nt++) {
                const uint32_t* p = Bs + (wx * 32 + nt * 8 + g) * SW + kc;
                bf[nt][0] = p[0];
                bf[nt][1] = p[4];
            }
#pragma unroll
            for (int mt = 0; mt < MT; mt++)
#pragma unroll
                for (int nt = 0; nt < 4; nt++)
                    mma_tf32(acc[mt][nt], af[mt], bf[nt]);
        }
    };

    // pipelined main loop
    load_regs(0);
    store_smem(0);
    if (nchunk > 1) load_regs(1);
    __syncthreads();
    for (int c = 0; c < nchunk; c++) {
        if (c + 1 < nchunk) store_smem((c + 1) & 1);
        if (c + 2 < nchunk) load_regs(c + 2);
        compute(c & 1);
        __syncthreads();
    }

    const int g = lane >> 2, tig = lane & 3;

    if (red_out) {
        float* red = (float*)smw;   // [4][ROWS]
#pragma unroll
        for (int mt = 0; mt < MT; mt++) {
            int rl0 = wy * (MT * 16) + mt * 16 + g;
            int rl1 = rl0 + 8;
            int b0 = (m0 + rl0) & 63, b1 = (m0 + rl1) & 63;
            float p0 = 0.f, p1 = 0.f;
#pragma unroll
            for (int nt = 0; nt < 4; nt++) {
                int col = n0 + wx * 32 + nt * 8 + tig * 2;
#pragma unroll
                for (int cc = 0; cc < 2; cc++) {
                    int cg = col + cc;
                    float bias = bias_n[cg];
                    float a0 = add_bh ? add_bh[(size_t)b0 * H_DIM + cg] : 0.f;
                    float a1 = add_bh ? add_bh[(size_t)b1 * H_DIM + cg] : 0.f;
                    float w0 = wgt_n ? wgt_n[cg] : wgt_bh[(size_t)b0 * H_DIM + cg];
                    float w1 = wgt_n ? wgt_n[cg] : wgt_bh[(size_t)b1 * H_DIM + cg];
                    p0 += w0 * tanhf(acc[mt][nt][cc]     + a0 + bias);
                    p1 += w1 * tanhf(acc[mt][nt][2 + cc] + a1 + bias);
                }
            }
            p0 += __shfl_xor_sync(0xffffffffu, p0, 1);
            p0 += __shfl_xor_sync(0xffffffffu, p0, 2);
            p1 += __shfl_xor_sync(0xffffffffu, p1, 1);
            p1 += __shfl_xor_sync(0xffffffffu, p1, 2);
            if (tig == 0) { red[wx * ROWS + rl0] = p0; red[wx * ROWS + rl1] = p1; }
        }
        __syncthreads();
        for (int r = tid; r < ROWS; r += 256) {
            float s = red[r] + red[ROWS + r] + red[2 * ROWS + r] + red[3 * ROWS + r];
            int m = m0 + r;
            red_out[(size_t)blockIdx.x * (B_DIM * T_DIM) + (m & 63) * T_DIM + (m >> 6)] = s;
        }
        return;
    }

    // plain store epilogue
#pragma unroll
    for (int mt = 0; mt < MT; mt++) {
        int row0 = m0 + wy * (MT * 16) + mt * 16 + g;
#pragma unroll
        for (int nt = 0; nt < 4; nt++) {
            int col = n0 + wx * 32 + nt * 8 + tig * 2;
            if (row0 < M_C) {
                *(float2*)&C[(size_t)row0 * ldc + col] = make_float2(acc[mt][nt][0], acc[mt][nt][1]);
                *(float2*)&C[(size_t)(row0 + 8) * ldc + col] = make_float2(acc[mt][nt][2], acc[mt][nt][3]);
            }
        }
    }
}

static constexpr int SMEM_MT4 = 2 * (128 * SW + 128 * SW) * 4;  // 73728
static constexpr int SMEM_MT2 = 2 * (64  * SW + 128 * SW) * 4;  // 55296

// ================= elementwise / reduction kernels =================

__global__ void k_zero(float* p, int n)
{
    for (int i = blockIdx.x * blockDim.x + threadIdx.x; i < n; i += gridDim.x * blockDim.x)
        p[i] = 0.0f;
}

// fused: alpha softmax (from partials) + ctx + build x = [emb[z], ctx]
// grid (B, 2): blockIdx.y selects h half [0,256) / [256,512)
__global__ void __launch_bounds__(256) k_attn(
    const float* __restrict__ part, const int* __restrict__ z,
    const float* __restrict__ emb,  const float* __restrict__ enc,
    float* __restrict__ ctx, float* __restrict__ x)
{
    int b = blockIdx.x, half = blockIdx.y, tid = threadIdx.x;
    __shared__ float al[T_DIM];
    __shared__ float sm[T_DIM];
    if (tid < T_DIM) {
        int idx = b * T_DIM + tid;
        float v = part[idx] + part[B_DIM * T_DIM + idx]
                + part[2 * B_DIM * T_DIM + idx] + part[3 * B_DIM * T_DIM + idx];
        al[tid] = v; sm[tid] = v;
    }
    __syncthreads();
    for (int o = 64; o > 0; o >>= 1) { if (tid < o) sm[tid] = fmaxf(sm[tid], sm[tid + o]); __syncthreads(); }
    float mx = sm[0]; __syncthreads();
    if (tid < T_DIM) { float e = expf(al[tid] - mx); al[tid] = e; sm[tid] = e; }
    __syncthreads();
    for (int o = 64; o > 0; o >>= 1) { if (tid < o) sm[tid] += sm[tid + o]; __syncthreads(); }
    float inv = 1.0f / sm[0];

    int h = half * 256 + tid;
    float acc = 0.0f;
#pragma unroll 4
    for (int t = 0; t < T_DIM; t++)
        acc += al[t] * enc[((size_t)t * B_DIM + b) * H_DIM + h];
    acc *= inv;
    ctx[b * H_DIM + h] = acc;
    x[(size_t)b * (E_DIM + H_DIM) + E_DIM + h] = acc;
    if (half == 0)
        x[(size_t)b * (E_DIM + H_DIM) + tid] = emb[(size_t)z[b] * E_DIM + tid];
}

__global__ void k_gru(const float* __restrict__ gi, const float* __restrict__ gh,
                      const float* __restrict__ bih, const float* __restrict__ bhh,
                      const float* __restrict__ h_prev, const float* __restrict__ ctx,
                      float* __restrict__ hnew, float* __restrict__ xp,
                      float* __restrict__ out)
{
    int b = blockIdx.x, h = threadIdx.x;
    const float* gib = gi + (size_t)b * 3 * H_DIM;
    const float* ghb = gh + (size_t)b * 3 * H_DIM;
    float ir  = gib[h]              + bih[h];
    float iz  = gib[H_DIM + h]      + bih[H_DIM + h];
    float in_ = gib[2 * H_DIM + h]  + bih[2 * H_DIM + h];
    float hr  = ghb[h]              + bhh[h];
    float hz  = ghb[H_DIM + h]      + bhh[H_DIM + h];
    float hn  = ghb[2 * H_DIM + h]  + bhh[2 * H_DIM + h];
    float r  = 1.0f / (1.0f + expf(-(ir + hr)));
    float zz = 1.0f / (1.0f + expf(-(iz + hz)));
    float n  = tanhf(in_ + r * hn);
    float hp = h_prev[b * H_DIM + h];
    float v  = (1.0f - zz) * n + zz * hp;
    hnew[b * H_DIM + h] = v;
    out[b * H_DIM + h] = v;
    out[B_DIM * H_DIM + b * H_DIM + h] = v;
    xp[b * 2 * H_DIM + h] = v;
    xp[b * 2 * H_DIM + H_DIM + h] = ctx[b * H_DIM + h];
}

// stats + parallel deterministic scatter; raw = sum of 4 partials
__global__ void k_copystats(const float* __restrict__ rpart, const int* __restrict__ u_input,
                            float* __restrict__ scat, float* __restrict__ stats)
{
    int b = blockIdx.x, t = threadIdx.x;
    int idx0 = b * T_DIM + t;
    __shared__ float sm[T_DIM];
    __shared__ float exm[T_DIM];
    __shared__ int   sidx[T_DIM];
    float v = rpart[idx0] + rpart[B_DIM * T_DIM + idx0]
            + rpart[2 * B_DIM * T_DIM + idx0] + rpart[3 * B_DIM * T_DIM + idx0];
    sm[t] = v; __syncthreads();
    for (int o = 64; o > 0; o >>= 1) { if (t < o) sm[t] = fmaxf(sm[t], sm[t + o]); __syncthreads(); }
    float cmax = sm[0]; __syncthreads();

    float e = expf(v - cmax);
    int tok = u_input[t * B_DIM + b];
    sidx[t] = (tok == 2) ? (V_DIM + t) : tok;
    float em = (tok != 0) ? e : 0.0f;
    exm[t] = em;

    sm[t] = e; __syncthreads();
    for (int o = 64; o > 0; o >>= 1) { if (t < o) sm[t] += sm[t + o]; __syncthreads(); }
    float total = sm[0]; __syncthreads();

    sm[t] = em; __syncthreads();
    for (int o = 64; o > 0; o >>= 1) { if (t < o) sm[t] += sm[t + o]; __syncthreads(); }
    float sum_exm = sm[0]; __syncthreads();

    int idx = sidx[t];
    bool first = true;
    for (int i = 0; i < t; i++) if (sidx[i] == idx) { first = false; break; }
    float a = 0.0f;
    if (first) {
        for (int i = t; i < T_DIM; i++) if (sidx[i] == idx) a += exm[i];
        scat[(size_t)b * VT_DIM + idx] = a;
    }
    sm[t] = a; __syncthreads();
    for (int o = 64; o > 0; o >>= 1) { if (t < o) sm[t] = fmaxf(sm[t], sm[t + o]); __syncthreads(); }
    if (t == 0) {
        stats[b * 8 + 0] = cmax;
        stats[b * 8 + 1] = total;
        stats[b * 8 + 2] = sum_exm;
        stats[b * 8 + 3] = sm[0];
    }
}

__global__ void k_reduce(const float* __restrict__ gen, const float* __restrict__ projb,
                         float* __restrict__ stats)
{
    int b = blockIdx.x, tid = threadIdx.x;
    float m = -1e30f, s = 0.0f;
    for (int v = tid; v < V_DIM; v += 512) {
        float l = gen[(size_t)b * V_DIM + v] + projb[v];
        float mn = fmaxf(m, l);
        s = s * expf(m - mn) + expf(l - mn);
        m = mn;
    }
    __shared__ float ms[512], ss[512];
    ms[tid] = m; ss[tid] = s; __syncthreads();
    for (int o = 256; o > 0; o >>= 1) {
        if (tid < o) {
            float m2 = ms[tid + o], s2 = ss[tid + o];
            float mn = fmaxf(ms[tid], m2);
            ss[tid] = ss[tid] * expf(ms[tid] - mn) + s2 * expf(m2 - mn);
            ms[tid] = mn;
        }
        __syncthreads();
    }
    if (tid == 0) {
        float cmax = stats[b * 8 + 0];
        float total = stats[b * 8 + 1];
        float sum_exm = stats[b * 8 + 2];
        float smax = stats[b * 8 + 3];
        float mg = ms[0], sg = ss[0];
        float mc = logf(EPSC * total + (1.0f - EPSC) * smax) + cmax;
        float M = fmaxf(mg, mc);
        float A = expf(cmax - M);
        float S = sg * expf(mg - M)
                + A * (EPSC * total * (float)VT_DIM + (1.0f - EPSC) * sum_exm);
        stats[b * 8 + 4] = M;
        stats[b * 8 + 5] = S;
        stats[b * 8 + 6] = A;
    }
}

__global__ void k_final(const float* __restrict__ gen, const float* __restrict__ projb,
                        const float* __restrict__ scat, const float* __restrict__ stats,
                        float* __restrict__ out)
{
    int i = blockIdx.x * blockDim.x + threadIdx.x;
    if (i >= B_DIM * VT_DIM) return;
    int b = i / VT_DIM;
    int j = i % VT_DIM;
    float M = stats[b * 8 + 4];
    float S = stats[b * 8 + 5];
    float A = stats[b * 8 + 6];
    float total = stats[b * 8 + 1];
    float val = A * (EPSC * total + (1.0f - EPSC) * scat[i]) / S;
    if (j < V_DIM)
        val += expf(gen[(size_t)b * V_DIM + j] + projb[j] - M) / S;
    out[2 * B_DIM * H_DIM + i] = val;
}

// ================= host launcher =================
extern "C" void kernel_launch(void* const* d_in, const int* in_sizes, int n_in,
                              void* d_out, int out_size)
{
    const float* u_enc  = (const float*)d_in[0];
    const int*   z_tm1  = (const int*)  d_in[1];
    const float* h0     = (const float*)d_in[2];
    const int*   u_inp  = (const int*)  d_in[3];
    const float* emb    = (const float*)d_in[4];
    const float* attn_W = (const float*)d_in[5];
    const float* attn_b = (const float*)d_in[6];
    const float* attn_v = (const float*)d_in[7];
    const float* gWih   = (const float*)d_in[8];
    const float* gWhh   = (const float*)d_in[9];
    const float* gbih   = (const float*)d_in[10];
    const float* gbhh   = (const float*)d_in[11];
    const float* projW  = (const float*)d_in[12];
    const float* projb  = (const float*)d_in[13];
    const float* c1W    = (const float*)d_in[14];
    const float* c1b    = (const float*)d_in[15];
    float* out = (float*)d_out;

    float* base = nullptr;
    cudaGetSymbolAddress((void**)&base, g_scratch);
    float* spart  = base + OFF_SPART;
    float* rpart  = base + OFF_RPART;
    float* hW1    = base + OFF_HW1;
    float* ctx    = base + OFF_CTX;
    float* x      = base + OFF_X;
    float* gi     = base + OFF_GI;
    float* gh     = base + OFF_GH;
    float* hnew   = base + OFF_HNEW;
    float* xp     = base + OFF_XP;
    float* gen    = base + OFF_GEN;
    float* scat   = base + OFF_SCAT;
    float* stats  = base + OFF_STATS;

    cudaFuncSetAttribute(tgemm<4>, cudaFuncAttributeMaxDynamicSharedMemorySize, SMEM_MT4);
    cudaFuncSetAttribute(tgemm<2>, cudaFuncAttributeMaxDynamicSharedMemorySize, SMEM_MT2);

    const int MROWS = T_DIM * B_DIM;  // 8192

    // 0) zero the dense scatter buffer
    k_zero<<<512, 256>>>(scat, B_DIM * VT_DIM);

    // 1) hW1 = h0 @ W1^T
    tgemm<2><<<dim3(H_DIM / 128, 1), 256, SMEM_MT2>>>(
        h0, attn_W, hW1, B_DIM, B_DIM, H_DIM, H_DIM, 2 * H_DIM, H_DIM,
        nullptr, nullptr, nullptr, nullptr, nullptr);

    // 2) energy GEMM with fused score reduction -> spart[4][B*T]
    tgemm<4><<<dim3(H_DIM / 128, MROWS / 128), 256, SMEM_MT4>>>(
        u_enc, attn_W + H_DIM, nullptr, MROWS, 0, H_DIM, H_DIM, 2 * H_DIM, 0,
        hW1, attn_b, attn_v, nullptr, spart);

    // 3) fused alpha softmax + ctx + x
    k_attn<<<dim3(B_DIM, 2), 256>>>(spart, z_tm1, emb, u_enc, ctx, x);

    // 4) GRU
    tgemm<2><<<dim3(3 * H_DIM / 128, 1), 256, SMEM_MT2>>>(
        x, gWih, gi, B_DIM, B_DIM, E_DIM + H_DIM, E_DIM + H_DIM, E_DIM + H_DIM, 3 * H_DIM,
        nullptr, nullptr, nullptr, nullptr, nullptr);
    tgemm<2><<<dim3(3 * H_DIM / 128, 1), 256, SMEM_MT2>>>(
        h0, gWhh, gh, B_DIM, B_DIM, H_DIM, H_DIM, H_DIM, 3 * H_DIM,
        nullptr, nullptr, nullptr, nullptr, nullptr);
    k_gru<<<B_DIM, H_DIM>>>(gi, gh, gbih, gbhh, h0, ctx, hnew, xp, out);

    // 5) copy GEMM with fused raw reduction -> rpart[4][B*T]
    tgemm<4><<<dim3(H_DIM / 128, MROWS / 128), 256, SMEM_MT4>>>(
        u_enc, c1W, nullptr, MROWS, 0, H_DIM, H_DIM, H_DIM, 0,
        nullptr, c1b, nullptr, hnew, rpart);
    k_copystats<<<B_DIM, T_DIM>>>(rpart, u_inp, scat, stats);

    // 6) gen_score = [h_new, ctx] @ proj_W^T
    tgemm<2><<<dim3(V_DIM / 128, 1), 256, SMEM_MT2>>>(
        xp, projW, gen, B_DIM, B_DIM, 2 * H_DIM, 2 * H_DIM, 2 * H_DIM, V_DIM,
        nullptr, nullptr, nullptr, nullptr, nullptr);

    // 7) global softmax reduction + final proba
    k_reduce<<<B_DIM, 512>>>(gen, projb, stats);
    k_final<<<(B_DIM * VT_DIM + 255) / 256, 256>>>(gen, projb, scat, stats, out);
}